// round 2
// baseline (speedup 1.0000x reference)
#include <cuda_runtime.h>
#include <cuda_bf16.h>
#include <cstdint>

// Problem constants
#define BB 4
#define TT 2048
#define CC 1024
#define HH 16
#define HS 64
#define MM (BB * TT)   // 8192

// Scratch buffers (device globals: allocation-free)
__device__ float g_q[BB * HH * TT * HS];
__device__ float g_k[BB * HH * TT * HS];
__device__ float g_v[BB * HH * TT * HS];
__device__ float g_y[MM * CC];

// ---------------------------------------------------------------------------
// GEMM: out = A[M,K] @ W[N,K]^T + bias[N]
// 128x128 tile, Ktile=16, 256 threads, 8x8 micro-tile.
// OUTMODE 0: out[m*N + n] (row-major [M,N])
// OUTMODE 1: out[((b*H + h)*T + t)*HS + d]  (q/k/v layout [B,H,T,HS])
// ---------------------------------------------------------------------------
template <int OUTMODE>
__global__ __launch_bounds__(256) void gemm_kernel(
    const float* __restrict__ A, const float* __restrict__ W,
    const float* __restrict__ bias, float* __restrict__ out)
{
    __shared__ float As[16][132];
    __shared__ float Bs[16][132];

    const int tid = threadIdx.x;
    const int tx = tid & 15;
    const int ty = tid >> 4;
    const int m0 = blockIdx.y * 128;
    const int n0 = blockIdx.x * 128;
    const int lr = tid >> 2;
    const int lq = (tid & 3) * 4;

    float acc[8][8];
#pragma unroll
    for (int i = 0; i < 8; i++)
#pragma unroll
        for (int j = 0; j < 8; j++) acc[i][j] = 0.0f;

    for (int k0 = 0; k0 < CC; k0 += 16) {
#pragma unroll
        for (int h = 0; h < 2; h++) {
            int r = lr + 64 * h;
            float4 a = *(const float4*)(A + (size_t)(m0 + r) * CC + k0 + lq);
            As[lq + 0][r] = a.x; As[lq + 1][r] = a.y;
            As[lq + 2][r] = a.z; As[lq + 3][r] = a.w;
            float4 b = *(const float4*)(W + (size_t)(n0 + r) * CC + k0 + lq);
            Bs[lq + 0][r] = b.x; Bs[lq + 1][r] = b.y;
            Bs[lq + 2][r] = b.z; Bs[lq + 3][r] = b.w;
        }
        __syncthreads();
#pragma unroll
        for (int k = 0; k < 16; k++) {
            float4 a0 = *(const float4*)&As[k][ty * 8];
            float4 a1 = *(const float4*)&As[k][ty * 8 + 4];
            float4 b0 = *(const float4*)&Bs[k][tx * 8];
            float4 b1 = *(const float4*)&Bs[k][tx * 8 + 4];
            float av[8] = {a0.x, a0.y, a0.z, a0.w, a1.x, a1.y, a1.z, a1.w};
            float bv[8] = {b0.x, b0.y, b0.z, b0.w, b1.x, b1.y, b1.z, b1.w};
#pragma unroll
            for (int i = 0; i < 8; i++)
#pragma unroll
                for (int j = 0; j < 8; j++) acc[i][j] += av[i] * bv[j];
        }
        __syncthreads();
    }

#pragma unroll
    for (int i = 0; i < 8; i++) {
        int m = m0 + ty * 8 + i;
#pragma unroll
        for (int j = 0; j < 8; j++) {
            int n = n0 + tx * 8 + j;
            float v = acc[i][j] + bias[n];
            if (OUTMODE == 0) {
                out[(size_t)m * CC + n] = v;
            } else {
                int b = m >> 11;       // m / T
                int t = m & (TT - 1);
                int h2 = n >> 6;       // n / HS
                int d = n & (HS - 1);
                out[(((size_t)(b * HH + h2)) * TT + t) * HS + d] = v;
            }
        }
    }
}

// ---------------------------------------------------------------------------
// Flash-attention (causal, fp32, online softmax)
// Block: 256 threads handling BM=64 queries x BN=64 keys per tile, HS=64.
// grid = (T/64, B*H).  Output written as [B,T,C] into g_y.
// ---------------------------------------------------------------------------
#define APAD 68

__global__ __launch_bounds__(256) void attn_kernel(
    const float* __restrict__ Q, const float* __restrict__ K,
    const float* __restrict__ V, float* __restrict__ Y)
{
    extern __shared__ float sm[];
    float (*Qs)[APAD] = (float(*)[APAD])(sm);
    float (*Ks)[APAD] = (float(*)[APAD])(sm + 64 * APAD);
    float (*Vs)[APAD] = (float(*)[APAD])(sm + 2 * 64 * APAD);
    float (*Ps)[APAD] = (float(*)[APAD])(sm + 3 * 64 * APAD);

    const int tid = threadIdx.x;
    const int tx = tid & 15;
    const int ty = tid >> 4;
    const int bh = blockIdx.y;
    const int qt = blockIdx.x;
    const int m0 = qt * 64;

    const float* Qb = Q + (size_t)bh * TT * HS;
    const float* Kb = K + (size_t)bh * TT * HS;
    const float* Vb = V + (size_t)bh * TT * HS;

    // Load Q tile [64,64]
    {
        int r = tid >> 2;
        int c = (tid & 3) * 16;
#pragma unroll
        for (int u = 0; u < 4; u++) {
            *(float4*)&Qs[r][c + u * 4] =
                *(const float4*)(Qb + (size_t)(m0 + r) * HS + c + u * 4);
        }
    }

    float mrow[4], lrow[4], acc[4][4];
#pragma unroll
    for (int i = 0; i < 4; i++) {
        mrow[i] = -1e30f;
        lrow[i] = 0.0f;
#pragma unroll
        for (int j = 0; j < 4; j++) acc[i][j] = 0.0f;
    }

    const float scale = 0.125f;  // 1/sqrt(64)

    for (int kt = 0; kt <= qt; kt++) {
        const int n0b = kt * 64;
        __syncthreads();  // prior PV / Q load complete before K/V overwrite
        {
            int r = tid >> 2;
            int c = (tid & 3) * 16;
#pragma unroll
            for (int u = 0; u < 4; u++) {
                *(float4*)&Ks[r][c + u * 4] =
                    *(const float4*)(Kb + (size_t)(n0b + r) * HS + c + u * 4);
                *(float4*)&Vs[r][c + u * 4] =
                    *(const float4*)(Vb + (size_t)(n0b + r) * HS + c + u * 4);
            }
        }
        __syncthreads();

        // S = Q K^T for 4x4 micro-tile
        float s[4][4];
#pragma unroll
        for (int i = 0; i < 4; i++)
#pragma unroll
            for (int j = 0; j < 4; j++) s[i][j] = 0.0f;

#pragma unroll
        for (int d = 0; d < HS; d += 4) {
            float4 a[4], b[4];
#pragma unroll
            for (int i = 0; i < 4; i++) a[i] = *(const float4*)&Qs[ty * 4 + i][d];
#pragma unroll
            for (int j = 0; j < 4; j++) b[j] = *(const float4*)&Ks[tx * 4 + j][d];
#pragma unroll
            for (int i = 0; i < 4; i++)
#pragma unroll
                for (int j = 0; j < 4; j++) {
                    s[i][j] += a[i].x * b[j].x + a[i].y * b[j].y +
                               a[i].z * b[j].z + a[i].w * b[j].w;
                }
        }

#pragma unroll
        for (int i = 0; i < 4; i++)
#pragma unroll
            for (int j = 0; j < 4; j++) s[i][j] *= scale;

        if (kt == qt) {  // causal mask only needed on the diagonal tile
#pragma unroll
            for (int i = 0; i < 4; i++)
#pragma unroll
                for (int j = 0; j < 4; j++) {
                    if (n0b + tx * 4 + j > m0 + ty * 4 + i) s[i][j] = -1e30f;
                }
        }

        // online softmax (row groups are 16 contiguous lanes sharing ty)
#pragma unroll
        for (int i = 0; i < 4; i++) {
            float rm = fmaxf(fmaxf(s[i][0], s[i][1]), fmaxf(s[i][2], s[i][3]));
#pragma unroll
            for (int o = 8; o >= 1; o >>= 1)
                rm = fmaxf(rm, __shfl_xor_sync(0xffffffffu, rm, o));
            float mnew = fmaxf(mrow[i], rm);
            float corr = __expf(mrow[i] - mnew);
            mrow[i] = mnew;
            float rs = 0.0f;
#pragma unroll
            for (int j = 0; j < 4; j++) {
                float p = __expf(s[i][j] - mnew);
                s[i][j] = p;
                rs += p;
            }
#pragma unroll
            for (int o = 8; o >= 1; o >>= 1)
                rs += __shfl_xor_sync(0xffffffffu, rs, o);
            lrow[i] = lrow[i] * corr + rs;
#pragma unroll
            for (int j = 0; j < 4; j++) acc[i][j] *= corr;
        }

        // stage P into smem for the PV GEMM
#pragma unroll
        for (int i = 0; i < 4; i++)
#pragma unroll
            for (int j = 0; j < 4; j++) Ps[ty * 4 + i][tx * 4 + j] = s[i][j];
        __syncthreads();

        // acc += P @ V
#pragma unroll 8
        for (int ss = 0; ss < 64; ss++) {
            float4 vv = *(const float4*)&Vs[ss][tx * 4];
            float p0 = Ps[ty * 4 + 0][ss];
            float p1 = Ps[ty * 4 + 1][ss];
            float p2 = Ps[ty * 4 + 2][ss];
            float p3 = Ps[ty * 4 + 3][ss];
            acc[0][0] += p0 * vv.x; acc[0][1] += p0 * vv.y;
            acc[0][2] += p0 * vv.z; acc[0][3] += p0 * vv.w;
            acc[1][0] += p1 * vv.x; acc[1][1] += p1 * vv.y;
            acc[1][2] += p1 * vv.z; acc[1][3] += p1 * vv.w;
            acc[2][0] += p2 * vv.x; acc[2][1] += p2 * vv.y;
            acc[2][2] += p2 * vv.z; acc[2][3] += p2 * vv.w;
            acc[3][0] += p3 * vv.x; acc[3][1] += p3 * vv.y;
            acc[3][2] += p3 * vv.z; acc[3][3] += p3 * vv.w;
        }
    }

    // write y as [B,T,C] (head-concat layout)
    const int b = bh >> 4;
    const int h = bh & 15;
#pragma unroll
    for (int i = 0; i < 4; i++) {
        float inv = 1.0f / lrow[i];
        int t = m0 + ty * 4 + i;
#pragma unroll
        for (int j = 0; j < 4; j++) {
            Y[((size_t)b * TT + t) * CC + h * HS + tx * 4 + j] = acc[i][j] * inv;
        }
    }
}

// ---------------------------------------------------------------------------
extern "C" void kernel_launch(void* const* d_in, const int* in_sizes, int n_in,
                              void* d_out, int out_size)
{
    const float* x  = (const float*)d_in[0];
    const float* Wq = (const float*)d_in[1];
    const float* bq = (const float*)d_in[2];
    const float* Wk = (const float*)d_in[3];
    const float* bk = (const float*)d_in[4];
    const float* Wv = (const float*)d_in[5];
    const float* bv = (const float*)d_in[6];
    const float* Wp = (const float*)d_in[7];
    const float* bp = (const float*)d_in[8];
    float* out = (float*)d_out;

    float *q, *k, *v, *y;
    cudaGetSymbolAddress((void**)&q, g_q);
    cudaGetSymbolAddress((void**)&k, g_k);
    cudaGetSymbolAddress((void**)&v, g_v);
    cudaGetSymbolAddress((void**)&y, g_y);

    dim3 ggrid(CC / 128, MM / 128);   // (8, 64)
    gemm_kernel<1><<<ggrid, 256>>>(x, Wq, bq, q);
    gemm_kernel<1><<<ggrid, 256>>>(x, Wk, bk, k);
    gemm_kernel<1><<<ggrid, 256>>>(x, Wv, bv, v);

    const int attn_smem = 4 * 64 * APAD * sizeof(float);  // 69632 B
    cudaFuncSetAttribute(attn_kernel, cudaFuncAttributeMaxDynamicSharedMemorySize,
                         attn_smem);
    dim3 agrid(TT / 64, BB * HH);     // (32, 64)
    attn_kernel<<<agrid, 256, attn_smem>>>(q, k, v, y);

    gemm_kernel<0><<<ggrid, 256>>>(y, Wp, bp, out);
}

// round 4
// speedup vs baseline: 3.6659x; 3.6659x over previous
#include <cuda_runtime.h>
#include <cstdint>

#define BB 4
#define TT 2048
#define CC 1024
#define HH 16
#define HSD 64
#define MM (BB * TT)   // 8192

// Scratch buffers (device globals: allocation-free)
__device__ float g_q[BB * HH * TT * HSD];
__device__ float g_k[BB * HH * TT * HSD];
__device__ float g_v[BB * HH * TT * HSD];
__device__ float g_y[MM * CC];

// ---------------------------------------------------------------------------
// helpers
// ---------------------------------------------------------------------------
__device__ __forceinline__ uint32_t smem_u32(const void* p) {
    uint32_t a;
    asm("{ .reg .u64 t; cvta.to.shared.u64 t, %1; cvt.u32.u64 %0, t; }"
        : "=r"(a) : "l"(p));
    return a;
}
__device__ __forceinline__ uint32_t tf32r(float x) {  // round-to-nearest tf32
    uint32_t u;
    asm("cvt.rna.tf32.f32 %0, %1;" : "=r"(u) : "f"(x));
    return u;
}
__device__ __forceinline__ float ex2f(float x) {
    float y;
    asm("ex2.approx.ftz.f32 %0, %1;" : "=f"(y) : "f"(x));
    return y;
}
__device__ __forceinline__ void mma_tf32(
    float& c0, float& c1, float& c2, float& c3,
    uint32_t a0, uint32_t a1, uint32_t a2, uint32_t a3,
    uint32_t b0, uint32_t b1)
{
    asm volatile(
        "mma.sync.aligned.m16n8k8.row.col.f32.tf32.tf32.f32 "
        "{%0,%1,%2,%3}, {%4,%5,%6,%7}, {%8,%9}, {%0,%1,%2,%3};"
        : "+f"(c0), "+f"(c1), "+f"(c2), "+f"(c3)
        : "r"(a0), "r"(a1), "r"(a2), "r"(a3), "r"(b0), "r"(b1));
}
#define CP_ASYNC16(s, g) \
    asm volatile("cp.async.cg.shared.global [%0], [%1], 16;" :: "r"(s), "l"(g))
#define CP_COMMIT() asm volatile("cp.async.commit_group;" ::: "memory")
#define CP_WAIT(n)  asm volatile("cp.async.wait_group %0;" :: "n"(n) : "memory")

// ---------------------------------------------------------------------------
// TF32 GEMM: out = A[M,K] @ W[N,K]^T + bias
// 128x128 tile, Kchunk=32, 2-stage cp.async, 8 warps (warp grid 4x2).
// smem row stride = 36 floats (conflict-free fragment LDS).
// ---------------------------------------------------------------------------
#define GST 36                      // row stride (floats)
#define STAGE_F (128 * GST)         // floats per matrix per stage

template <int OUTMODE>
__global__ __launch_bounds__(256) void gemm_tc(
    const float* __restrict__ A, const float* __restrict__ W,
    const float* __restrict__ bias, float* __restrict__ out)
{
    extern __shared__ float sm[];
    // layout: [A0][B0][A1][B1]
    const int tid  = threadIdx.x;
    const int lane = tid & 31;
    const int warp = tid >> 5;
    const int wm = warp >> 1;        // 0..3
    const int wn = warp & 1;         // 0..1
    const int m0 = blockIdx.y * 128;
    const int n0 = blockIdx.x * 128;

    const uint32_t sbase = smem_u32(sm);

    float acc[2][8][4];
#pragma unroll
    for (int t = 0; t < 2; t++)
#pragma unroll
        for (int j = 0; j < 8; j++)
#pragma unroll
            for (int e = 0; e < 4; e++) acc[t][j][e] = 0.0f;

    auto load_stage = [&](int s, int k0) {
        uint32_t sA = sbase + (uint32_t)(2 * s) * STAGE_F * 4;
        uint32_t sB = sA + STAGE_F * 4;
#pragma unroll
        for (int i = 0; i < 4; i++) {
            int linear = i * 256 + tid;         // 0..1023
            int row = linear >> 3;              // 0..127
            int c4  = (linear & 7) << 2;        // 0,4,...,28
            CP_ASYNC16(sA + (uint32_t)(row * GST + c4) * 4,
                       A + (size_t)(m0 + row) * CC + k0 + c4);
            CP_ASYNC16(sB + (uint32_t)(row * GST + c4) * 4,
                       W + (size_t)(n0 + row) * CC + k0 + c4);
        }
    };

    load_stage(0, 0);
    CP_COMMIT();

    for (int kt = 0; kt < CC / 32; kt++) {
        if (kt + 1 < CC / 32) {
            load_stage((kt + 1) & 1, (kt + 1) * 32);
            CP_COMMIT();
            CP_WAIT(1);
        } else {
            CP_WAIT(0);
        }
        __syncthreads();

        const float* As = sm + (size_t)(2 * (kt & 1)) * STAGE_F;
        const float* Bs = As + STAGE_F;
        const int r4 = lane >> 2;    // 0..7
        const int c4 = lane & 3;     // 0..3

#pragma unroll
        for (int ks = 0; ks < 4; ks++) {
            const int ko = ks * 8;
            uint32_t af[2][4];
#pragma unroll
            for (int t = 0; t < 2; t++) {
                const float* ar = As + (wm * 32 + t * 16 + r4) * GST + ko + c4;
                af[t][0] = tf32r(ar[0]);
                af[t][1] = tf32r(ar[8 * GST]);
                af[t][2] = tf32r(ar[4]);
                af[t][3] = tf32r(ar[8 * GST + 4]);
            }
#pragma unroll
            for (int j = 0; j < 8; j++) {
                const float* br = Bs + (wn * 64 + j * 8 + r4) * GST + ko + c4;
                uint32_t b0 = tf32r(br[0]);
                uint32_t b1 = tf32r(br[4]);
#pragma unroll
                for (int t = 0; t < 2; t++)
                    mma_tf32(acc[t][j][0], acc[t][j][1], acc[t][j][2], acc[t][j][3],
                             af[t][0], af[t][1], af[t][2], af[t][3], b0, b1);
            }
        }
        __syncthreads();
    }

    // epilogue
#pragma unroll
    for (int t = 0; t < 2; t++) {
        int r0 = m0 + wm * 32 + t * 16 + (lane >> 2);
#pragma unroll
        for (int j = 0; j < 8; j++) {
            int n = n0 + wn * 64 + j * 8 + (lane & 3) * 2;
            float bs0 = bias[n], bs1 = bias[n + 1];
#pragma unroll
            for (int half = 0; half < 2; half++) {
                int m = r0 + half * 8;
                float v0 = acc[t][j][half * 2 + 0] + bs0;
                float v1 = acc[t][j][half * 2 + 1] + bs1;
                if (OUTMODE == 0) {
                    *(float2*)&out[(size_t)m * CC + n] = make_float2(v0, v1);
                } else {
                    int b  = m >> 11;
                    int tt = m & (TT - 1);
                    int h2 = n >> 6;
                    int d  = n & (HSD - 1);
                    *(float2*)&out[(((size_t)(b * HH + h2)) * TT + tt) * HSD + d] =
                        make_float2(v0, v1);
                }
            }
        }
    }
}

// ---------------------------------------------------------------------------
// Flash attention, tf32 tensor-core version.
// BM=128 (8 warps x m16), BN=64, HS=64. grid = (T/128, B*H).
// Q prescaled by (1/8)*log2(e); softmax in exp2 domain.
// smem row stride 68 floats (conflict-free fragment LDS).
// ---------------------------------------------------------------------------
#define AST 68

__global__ __launch_bounds__(256) void attn_tc(
    const float* __restrict__ Q, const float* __restrict__ K,
    const float* __restrict__ V, float* __restrict__ Y)
{
    extern __shared__ float sm[];
    float* Qs = sm;                       // 128 x AST
    float* Ks = Qs + 128 * AST;           // 64 x AST
    float* Vs = Ks + 64 * AST;            // 64 x AST
    float* Ps = Vs + 64 * AST;            // 128 x AST

    const int tid  = threadIdx.x;
    const int lane = tid & 31;
    const int warp = tid >> 5;            // 0..7, owns rows warp*16..+15
    const int bh = blockIdx.y;
    const int qt = blockIdx.x;
    const int m0 = qt * 128;

    const float* Qb = Q + (size_t)bh * TT * HSD;
    const float* Kb = K + (size_t)bh * TT * HSD;
    const float* Vb = V + (size_t)bh * TT * HSD;

    const float qscale = 0.125f * 1.44269504f;

    // load Q tile, prescaled
#pragma unroll
    for (int i = 0; i < 8; i++) {
        int id = i * 256 + tid;           // 0..2047 float4 ids
        int r = id >> 4;
        int c = (id & 15) << 2;
        float4 v = *(const float4*)(Qb + (size_t)(m0 + r) * HSD + c);
        v.x *= qscale; v.y *= qscale; v.z *= qscale; v.w *= qscale;
        *(float4*)&Qs[r * AST + c] = v;
    }

    float o[8][4];
    float mrow[2] = {-1e30f, -1e30f};
    float lrow[2] = {0.0f, 0.0f};
#pragma unroll
    for (int j = 0; j < 8; j++)
#pragma unroll
        for (int e = 0; e < 4; e++) o[j][e] = 0.0f;

    const int r4 = lane >> 2;
    const int c4 = lane & 3;
    const int n_tiles = 2 * (qt + 1);

    for (int kt = 0; kt < n_tiles; kt++) {
        const int s0 = kt * 64;
        __syncthreads();   // previous iter's smem reads complete
#pragma unroll
        for (int i = 0; i < 4; i++) {
            int id = i * 256 + tid;       // 0..1023
            int r = id >> 4;
            int c = (id & 15) << 2;
            *(float4*)&Ks[r * AST + c] =
                *(const float4*)(Kb + (size_t)(s0 + r) * HSD + c);
            *(float4*)&Vs[r * AST + c] =
                *(const float4*)(Vb + (size_t)(s0 + r) * HSD + c);
        }
        __syncthreads();

        // ---- S = Q K^T (in log2 units) ----
        float s[8][4];
#pragma unroll
        for (int j = 0; j < 8; j++)
#pragma unroll
            for (int e = 0; e < 4; e++) s[j][e] = 0.0f;

#pragma unroll
        for (int ks = 0; ks < 8; ks++) {
            const int ko = ks * 8;
            const float* ar = Qs + (warp * 16 + r4) * AST + ko + c4;
            uint32_t a0 = tf32r(ar[0]);
            uint32_t a1 = tf32r(ar[8 * AST]);
            uint32_t a2 = tf32r(ar[4]);
            uint32_t a3 = tf32r(ar[8 * AST + 4]);
#pragma unroll
            for (int j = 0; j < 8; j++) {
                const float* br = Ks + (j * 8 + r4) * AST + ko + c4;
                uint32_t b0 = tf32r(br[0]);
                uint32_t b1 = tf32r(br[4]);
                mma_tf32(s[j][0], s[j][1], s[j][2], s[j][3],
                         a0, a1, a2, a3, b0, b1);
            }
        }

        // ---- causal mask (only needed on the last two tiles) ----
        if (kt >= 2 * qt) {
            int gr0 = m0 + warp * 16 + r4;
#pragma unroll
            for (int j = 0; j < 8; j++) {
                int gc = s0 + j * 8 + c4 * 2;
                if (gc > gr0)     s[j][0] = -1e30f;
                if (gc + 1 > gr0) s[j][1] = -1e30f;
                if (gc > gr0 + 8)     s[j][2] = -1e30f;
                if (gc + 1 > gr0 + 8) s[j][3] = -1e30f;
            }
        }

        // ---- online softmax (each thread covers rows r0, r0+8; 4 lanes/row) ----
        float rm0 = -1e30f, rm1 = -1e30f;
#pragma unroll
        for (int j = 0; j < 8; j++) {
            rm0 = fmaxf(rm0, fmaxf(s[j][0], s[j][1]));
            rm1 = fmaxf(rm1, fmaxf(s[j][2], s[j][3]));
        }
#pragma unroll
        for (int off = 1; off <= 2; off <<= 1) {
            rm0 = fmaxf(rm0, __shfl_xor_sync(0xffffffffu, rm0, off));
            rm1 = fmaxf(rm1, __shfl_xor_sync(0xffffffffu, rm1, off));
        }
        float mn0 = fmaxf(mrow[0], rm0);
        float mn1 = fmaxf(mrow[1], rm1);
        float co0 = ex2f(mrow[0] - mn0);
        float co1 = ex2f(mrow[1] - mn1);
        mrow[0] = mn0; mrow[1] = mn1;

        float rs0 = 0.0f, rs1 = 0.0f;
#pragma unroll
        for (int j = 0; j < 8; j++) {
            s[j][0] = ex2f(s[j][0] - mn0); rs0 += s[j][0];
            s[j][1] = ex2f(s[j][1] - mn0); rs0 += s[j][1];
            s[j][2] = ex2f(s[j][2] - mn1); rs1 += s[j][2];
            s[j][3] = ex2f(s[j][3] - mn1); rs1 += s[j][3];
        }
#pragma unroll
        for (int off = 1; off <= 2; off <<= 1) {
            rs0 += __shfl_xor_sync(0xffffffffu, rs0, off);
            rs1 += __shfl_xor_sync(0xffffffffu, rs1, off);
        }
        lrow[0] = lrow[0] * co0 + rs0;
        lrow[1] = lrow[1] * co1 + rs1;
#pragma unroll
        for (int j = 0; j < 8; j++) {
            o[j][0] *= co0; o[j][1] *= co0;
            o[j][2] *= co1; o[j][3] *= co1;
        }

        // ---- stage P (same-warp producer/consumer) ----
        {
            int pr0 = warp * 16 + r4;
            int pc  = c4 * 2;
#pragma unroll
            for (int j = 0; j < 8; j++) {
                *(float2*)&Ps[pr0 * AST + j * 8 + pc]       = make_float2(s[j][0], s[j][1]);
                *(float2*)&Ps[(pr0 + 8) * AST + j * 8 + pc] = make_float2(s[j][2], s[j][3]);
            }
        }
        __syncwarp();

        // ---- O += P @ V ----
#pragma unroll
        for (int ks = 0; ks < 8; ks++) {
            const int ko = ks * 8;
            const float* ar = Ps + (warp * 16 + r4) * AST + ko + c4;
            uint32_t a0 = tf32r(ar[0]);
            uint32_t a1 = tf32r(ar[8 * AST]);
            uint32_t a2 = tf32r(ar[4]);
            uint32_t a3 = tf32r(ar[8 * AST + 4]);
#pragma unroll
            for (int j = 0; j < 8; j++) {
                const float* br = Vs + (ko + c4) * AST + j * 8 + r4;
                uint32_t b0 = tf32r(br[0]);
                uint32_t b1 = tf32r(br[4 * AST]);
                mma_tf32(o[j][0], o[j][1], o[j][2], o[j][3],
                         a0, a1, a2, a3, b0, b1);
            }
        }
    }

    // ---- epilogue: y[b, t, h*64 + d] ----
    const int b = bh >> 4;
    const int h = bh & 15;
    float inv0 = 1.0f / lrow[0];
    float inv1 = 1.0f / lrow[1];
    int t0 = m0 + warp * 16 + r4;
#pragma unroll
    for (int j = 0; j < 8; j++) {
        int d = h * HSD + j * 8 + c4 * 2;
        *(float2*)&Y[((size_t)b * TT + t0) * CC + d] =
            make_float2(o[j][0] * inv0, o[j][1] * inv0);
        *(float2*)&Y[((size_t)b * TT + t0 + 8) * CC + d] =
            make_float2(o[j][2] * inv1, o[j][3] * inv1);
    }
}

// ---------------------------------------------------------------------------
extern "C" void kernel_launch(void* const* d_in, const int* in_sizes, int n_in,
                              void* d_out, int out_size)
{
    const float* x  = (const float*)d_in[0];
    const float* Wq = (const float*)d_in[1];
    const float* bq = (const float*)d_in[2];
    const float* Wk = (const float*)d_in[3];
    const float* bk = (const float*)d_in[4];
    const float* Wv = (const float*)d_in[5];
    const float* bv = (const float*)d_in[6];
    const float* Wp = (const float*)d_in[7];
    const float* bp = (const float*)d_in[8];
    float* out = (float*)d_out;

    float *q, *k, *v, *y;
    cudaGetSymbolAddress((void**)&q, g_q);
    cudaGetSymbolAddress((void**)&k, g_k);
    cudaGetSymbolAddress((void**)&v, g_v);
    cudaGetSymbolAddress((void**)&y, g_y);

    const int gemm_smem = 4 * STAGE_F * sizeof(float);          // 73728
    cudaFuncSetAttribute(gemm_tc<0>, cudaFuncAttributeMaxDynamicSharedMemorySize, gemm_smem);
    cudaFuncSetAttribute(gemm_tc<1>, cudaFuncAttributeMaxDynamicSharedMemorySize, gemm_smem);

    dim3 ggrid(CC / 128, MM / 128);   // (8, 64)
    gemm_tc<1><<<ggrid, 256, gemm_smem>>>(x, Wq, bq, q);
    gemm_tc<1><<<ggrid, 256, gemm_smem>>>(x, Wk, bk, k);
    gemm_tc<1><<<ggrid, 256, gemm_smem>>>(x, Wv, bv, v);

    const int attn_smem = (128 + 64 + 64 + 128) * AST * sizeof(float);  // 104448
    cudaFuncSetAttribute(attn_tc, cudaFuncAttributeMaxDynamicSharedMemorySize, attn_smem);
    dim3 agrid(TT / 128, BB * HH);    // (16, 64)
    attn_tc<<<agrid, 256, attn_smem>>>(q, k, v, y);

    gemm_tc<0><<<ggrid, 256, gemm_smem>>>(y, Wp, bp, out);
}